// round 16
// baseline (speedup 1.0000x reference)
#include <cuda_runtime.h>
#include <cuda_fp16.h>
#include <cstdint>

#define WINDOW   512
#define PREFIX   16
#define SEQ      4096
#define NH       16
#define BATCH    2
#define DM       1024
#define HD       64

#define NX  ((size_t)BATCH * SEQ * DM)
#define NW1 ((size_t)3 * DM * DM)
#define NW2 ((size_t)DM * DM)

// Scratch (device globals; allocation APIs are forbidden). All fp16.
__device__ __half g_q [(size_t)BATCH * NH * SEQ * HD];  // pre-scaled 0.125*log2e, [bh][s][d]
__device__ __half g_k [(size_t)BATCH * NH * SEQ * HD];  // [bh][s][d]
__device__ __half g_vt[(size_t)BATCH * NH * HD * SEQ];  // TRANSPOSED [bh][d][s]
__device__ __half g_o [(size_t)BATCH * SEQ * DM];       // [b][s][h*64+d]
__device__ __half g_x [NX];                             // fp16 copy of x
__device__ __half g_w1[NW1];                            // fp16 copy of w_qkv
__device__ __half g_w2[NW2];                            // fp16 copy of w_out

// ---------------------------------------------------------------------------
__device__ __forceinline__ void cp_async16(unsigned smem_dst, const void* gsrc) {
    asm volatile("cp.async.cg.shared.global [%0], [%1], 16;\n" :: "r"(smem_dst), "l"(gsrc));
}
__device__ __forceinline__ void cp_commit() { asm volatile("cp.async.commit_group;\n"); }
template<int N>
__device__ __forceinline__ void cp_wait() {
    asm volatile("cp.async.wait_group %0;\n" :: "n"(N));
}

__device__ __forceinline__ void mma_f16(float* c, const unsigned* a, const unsigned* b) {
    asm volatile(
        "mma.sync.aligned.m16n8k16.row.col.f32.f16.f16.f32 "
        "{%0,%1,%2,%3}, {%4,%5,%6,%7}, {%8,%9}, {%0,%1,%2,%3};\n"
        : "+f"(c[0]), "+f"(c[1]), "+f"(c[2]), "+f"(c[3])
        : "r"(a[0]), "r"(a[1]), "r"(a[2]), "r"(a[3]), "r"(b[0]), "r"(b[1]));
}

__device__ __forceinline__ void ldsm4(unsigned& r0, unsigned& r1, unsigned& r2, unsigned& r3,
                                      unsigned addr) {
    asm volatile("ldmatrix.sync.aligned.m8n8.x4.shared.b16 {%0,%1,%2,%3}, [%4];"
                 : "=r"(r0), "=r"(r1), "=r"(r2), "=r"(r3) : "r"(addr));
}

__device__ __forceinline__ float ex2f(float x) {
    float r;
    asm("ex2.approx.ftz.f32 %0, %1;" : "=f"(r) : "f"(x));
    return r;
}

// ---------------------------------------------------------------------------
// Prep: fp16-convert x, w_qkv, w_out into scratch.
// ---------------------------------------------------------------------------
__global__ __launch_bounds__(256)
void prep_f16(const float* __restrict__ x,
              const float* __restrict__ wq,
              const float* __restrict__ wo)
{
    size_t i = (size_t)blockIdx.x * 256 + threadIdx.x;
    const size_t nx = NX / 4, nw1 = NW1 / 4;
    const float4* src;
    __half* dst;
    size_t j;
    if (i < nx)            { src = (const float4*)x;  dst = g_x;  j = i; }
    else if (i < nx + nw1) { src = (const float4*)wq; dst = g_w1; j = i - nx; }
    else                   { src = (const float4*)wo; dst = g_w2; j = i - nx - nw1; }
    float4 v = src[j];
    *(__half2*)(dst + 4 * j)     = __floats2half2_rn(v.x, v.y);
    *(__half2*)(dst + 4 * j + 2) = __floats2half2_rn(v.z, v.w);
}

// ---------------------------------------------------------------------------
// FP16 tensor-core GEMM (NT): round-11 shape (the best of six variants).
// 3-stage cp.async pipeline, XOR-swizzled smem, ldmatrix, m16n8k16.
// Block 128x128, 8 warps (2m x 4n), warp tile 64x32, KT=64.
// Rows are 128 B (64 fp16); 16B chunk c at row r lives at phys chunk c^(r&7).
// ---------------------------------------------------------------------------
#define KT     64
#define NTILE  (1024 / KT)                  // 16
#define NSTG   3
#define TILEB  (128 * 128)                  // 16384 bytes per matrix per stage
#define GEMM_SMEM (NSTG * 2 * TILEB)        // 98304 bytes

#define QSCALE 0.18033688f                  // 0.125 * log2(e)  (base-2 softmax)

template<bool QKV>
__global__ __launch_bounds__(256, 2)
void gemm_f16(float* __restrict__ Cout)
{
    extern __shared__ char smc[];

    const __half* A = QKV ? g_x  : g_o;
    const __half* B = QKV ? g_w1 : g_w2;

    const int tid  = threadIdx.x;
    const int lane = tid & 31;
    const int wid  = tid >> 5;
    const int wm   = wid >> 2;
    const int wn   = wid & 3;
    const int m0   = blockIdx.y << 7;
    const int n0   = blockIdx.x << 7;
    const int g    = lane >> 2;
    const int t    = lane & 3;
    const int r8   = lane & 7;
    const int sel  = lane >> 3;

    float acc[4][4][4];
    #pragma unroll
    for (int i = 0; i < 4; ++i)
        #pragma unroll
        for (int j = 0; j < 4; ++j)
            #pragma unroll
            for (int r = 0; r < 4; ++r) acc[i][j][r] = 0.0f;

    const unsigned sA = (unsigned)__cvta_generic_to_shared(smc);
    const unsigned sB = sA + NSTG * TILEB;

    const unsigned aRow = (unsigned)((wm * 64 + ((sel & 1) << 3) + r8) * 128);
    const unsigned bRow = (unsigned)((wn * 32 + ((sel >> 1) << 3) + r8) * 128);
    const int ac = sel >> 1;    // A chunk half (k 0-7 vs 8-15 within k16)
    const int bc = sel & 1;     // B chunk half

    #define GSTAGE(k0, s)                                                        \
        do {                                                                     \
            _Pragma("unroll")                                                    \
            for (int it2 = 0; it2 < 4; ++it2) {                                  \
                int idx = tid + (it2 << 8);                                      \
                int row = idx >> 3;                                              \
                int c   = idx & 7;                                               \
                unsigned off = (unsigned)(row * 128 + ((c ^ (row & 7)) << 4))    \
                             + (unsigned)(s) * TILEB;                            \
                cp_async16(sA + off, A + (size_t)(m0 + row) * 1024 + (k0) + c * 8); \
                cp_async16(sB + off, B + (size_t)(n0 + row) * 1024 + (k0) + c * 8); \
            }                                                                    \
            cp_commit();                                                         \
        } while (0)

    GSTAGE(0 * KT, 0);
    GSTAGE(1 * KT, 1);

    for (int kt = 0; kt < NTILE; ++kt) {
        if (kt < NTILE - 1) cp_wait<1>();
        else                cp_wait<0>();
        __syncthreads();
        if (kt + 2 < NTILE) GSTAGE((kt + 2) * KT, (kt + 2) % NSTG);

        const unsigned aT = sA + (unsigned)(kt % NSTG) * TILEB;
        const unsigned bT = sB + (unsigned)(kt % NSTG) * TILEB;

        #pragma unroll
        for (int kg = 0; kg < 4; ++kg) {          // 4 x k16 per tile
            const unsigned axc = (unsigned)(((2 * kg + ac) ^ r8) << 4);
            const unsigned bxc = (unsigned)(((2 * kg + bc) ^ r8) << 4);
            unsigned af[4][4];
            #pragma unroll
            for (int im = 0; im < 4; ++im)
                ldsm4(af[im][0], af[im][1], af[im][2], af[im][3],
                      aT + aRow + (unsigned)(im * 2048) + axc);
            #pragma unroll
            for (int p = 0; p < 2; ++p) {
                unsigned b0[2], b1[2];
                ldsm4(b0[0], b0[1], b1[0], b1[1],
                      bT + bRow + (unsigned)(p * 2048) + bxc);
                #pragma unroll
                for (int im = 0; im < 4; ++im) {
                    mma_f16(acc[im][2 * p],     af[im], b0);
                    mma_f16(acc[im][2 * p + 1], af[im], b1);
                }
            }
        }
    }

    #pragma unroll
    for (int im = 0; im < 4; ++im) {
        #pragma unroll
        for (int jn = 0; jn < 4; ++jn) {
            int row = m0 + wm * 64 + im * 16 + g;
            int col = n0 + wn * 32 + jn * 8 + (t << 1);
            if (QKV) {
                int part = col >> 10;            // 0:q 1:k 2:v
                float sc = (part == 0) ? QSCALE : 1.0f;
                __half2 h0 = __floats2half2_rn(acc[im][jn][0] * sc, acc[im][jn][1] * sc);
                __half2 h1 = __floats2half2_rn(acc[im][jn][2] * sc, acc[im][jn][3] * sc);
                int nn = col & 1023;
                int h  = nn >> 6;
                int d  = nn & 63;
                int bb = row >> 12, s = row & 4095;
                if (part == 2) {
                    __half* dst = g_vt + ((size_t)(bb * NH + h) * HD + d) * SEQ + s;
                    dst[0]       = __low2half(h0);
                    dst[SEQ]     = __high2half(h0);
                    dst[8]       = __low2half(h1);
                    dst[SEQ + 8] = __high2half(h1);
                } else {
                    __half* dst = (part == 0) ? g_q : g_k;
                    size_t base = (((size_t)(bb * NH + h)) * SEQ) * HD + d;
                    *(__half2*)(dst + base + (size_t)s * HD)       = h0;
                    *(__half2*)(dst + base + (size_t)(s + 8) * HD) = h1;
                }
            } else {
                *(float2*)(Cout + (size_t)row * DM + col) =
                    make_float2(acc[im][jn][0], acc[im][jn][1]);
                *(float2*)(Cout + (size_t)(row + 8) * DM + col) =
                    make_float2(acc[im][jn][2], acc[im][jn][3]);
            }
        }
    }
    #undef GSTAGE
}

// ---------------------------------------------------------------------------
// FP16 tensor-core flash attention: 256 queries/block (amortizes the 511-key
// window halo: 13 key-tiles per 256 queries vs 22 at 128q), 512 threads =
// 16 warps x 16 query rows. Q in registers, cp.async double-buffered K/V^T,
// ldmatrix, m16n8k16, base-2 softmax.
// Smem: K[2][64][128B] | Vt[2][64][128B] | P[256][128B]  (XOR-swizzled rows)
// ---------------------------------------------------------------------------
#define QB    256
#define KVB   8192
#define SM_PB (4 * KVB)                    // 32768
#define ATT_SMEM (SM_PB + QB * 128)        // 65536 bytes

__global__ __launch_bounds__(512, 1)
void attn_f16()
{
    extern __shared__ char smc[];
    __half* Psh = (__half*)(smc + SM_PB);

    const int tid  = threadIdx.x;
    const int lane = tid & 31;
    const int w    = tid >> 5;                    // 0..15
    const int g    = lane >> 2;
    const int t    = lane & 3;
    const int r8   = lane & 7;
    const int sel  = lane >> 3;
    const int bh   = blockIdx.y;
    const int t0   = blockIdx.x << 8;             // 256 queries per block

    const __half* Kg  = g_k  + (size_t)bh * SEQ * HD;
    const __half* Vtg = g_vt + (size_t)bh * HD * SEQ;

    const unsigned sbase = (unsigned)__cvta_generic_to_shared(smc);

    const unsigned kRow = (unsigned)((((sel >> 1) << 3) + r8) * 128);
    const unsigned pRow = (unsigned)((w * 16 + ((sel & 1) << 3) + r8) * 128);
    const int bc = sel & 1;
    const int ac = sel >> 1;

    const int rmin = t0 + w * 16;
    const int r0 = rmin + g;
    const int r1 = r0 + 8;

    unsigned qa[4][4];
    {
        const __half* q0 = g_q + (size_t)bh * SEQ * HD + (size_t)r0 * HD;
        #pragma unroll
        for (int kg = 0; kg < 4; ++kg) {
            qa[kg][0] = *(const unsigned*)(q0 + kg * 16 + 2 * t);
            qa[kg][1] = *(const unsigned*)(q0 + 512 + kg * 16 + 2 * t);   // +8 rows
            qa[kg][2] = *(const unsigned*)(q0 + kg * 16 + 2 * t + 8);
            qa[kg][3] = *(const unsigned*)(q0 + 512 + kg * 16 + 2 * t + 8);
        }
    }

    // Stage K tile (rows=key) and Vt tile (rows=d): 512 chunks each -> 1/thread
    #define ASTAGE(kbase, s)                                                     \
        do {                                                                     \
            int row = tid >> 3;                                                  \
            int c   = tid & 7;                                                   \
            unsigned off = (unsigned)(row * 128 + ((c ^ (row & 7)) << 4))        \
                         + (unsigned)(s) * KVB;                                  \
            cp_async16(sbase + off,            Kg  + (size_t)((kbase) + row) * 64 + c * 8); \
            cp_async16(sbase + off + 2 * KVB,  Vtg + (size_t)row * SEQ + (kbase) + c * 8);  \
            cp_commit();                                                         \
        } while (0)

    float oa[8][4];
    #pragma unroll
    for (int j = 0; j < 8; ++j)
        #pragma unroll
        for (int r = 0; r < 4; ++r) oa[j][r] = 0.0f;
    float m0 = -1e30f, m1 = -1e30f, l0 = 0.0f, l1 = 0.0f;

    int lo = t0 - (WINDOW - 1); if (lo < 0) lo = 0;
    const int lo_tile = lo >> 6;
    const int hi_tile = (t0 + QB - 1) >> 6;
    const int extra   = (lo_tile > 0) ? 1 : 0;
    const int ntiles  = hi_tile - lo_tile + 1 + extra;

    #define KBASE(i) ((extra ? (((i) == 0) ? 0 : (lo_tile + (i) - 1)) : (lo_tile + (i))) << 6)

    ASTAGE(KBASE(0), 0);

    int buf = 0;
    for (int it = 0; it < ntiles; ++it) {
        const int kbase = KBASE(it);
        cp_wait<0>();
        __syncthreads();
        if (it + 1 < ntiles) ASTAGE(KBASE(it + 1), buf ^ 1);

        const unsigned kT = sbase + (unsigned)buf * KVB;
        const unsigned vT = kT + 2 * KVB;

        // S = Q K^T : 16 x 64 per warp
        float sc[8][4];
        #pragma unroll
        for (int j = 0; j < 8; ++j)
            #pragma unroll
            for (int r = 0; r < 4; ++r) sc[j][r] = 0.0f;

        #pragma unroll
        for (int kg = 0; kg < 4; ++kg) {
            const unsigned bxc = (unsigned)(((2 * kg + bc) ^ r8) << 4);
            #pragma unroll
            for (int p = 0; p < 4; ++p) {
                unsigned b0[2], b1[2];
                ldsm4(b0[0], b0[1], b1[0], b1[1],
                      kT + kRow + (unsigned)(p * 2048) + bxc);
                mma_f16(sc[2 * p],     qa[kg], b0);
                mma_f16(sc[2 * p + 1], qa[kg], b1);
            }
        }

        // Mask (skipped for fully-unmasked warp tiles) + base-2 online softmax
        const bool full = (kbase + 63 <= rmin) && ((rmin + 15 - kbase) < WINDOW);
        if (!full) {
            #pragma unroll
            for (int j = 0; j < 8; ++j) {
                int kc0 = kbase + j * 8 + (t << 1);
                int kc1 = kc0 + 1;
                bool a00 = (kc0 <= r0) && ((kc0 < PREFIX) || ((r0 - kc0) < WINDOW));
                bool a01 = (kc1 <= r0) && ((kc1 < PREFIX) || ((r0 - kc1) < WINDOW));
                bool a10 = (kc0 <= r1) && ((kc0 < PREFIX) || ((r1 - kc0) < WINDOW));
                bool a11 = (kc1 <= r1) && ((kc1 < PREFIX) || ((r1 - kc1) < WINDOW));
                if (!a00) sc[j][0] = -1e30f;
                if (!a01) sc[j][1] = -1e30f;
                if (!a10) sc[j][2] = -1e30f;
                if (!a11) sc[j][3] = -1e30f;
            }
        }
        float rmax0 = -1e30f, rmax1 = -1e30f;
        #pragma unroll
        for (int j = 0; j < 8; ++j) {
            rmax0 = fmaxf(rmax0, fmaxf(sc[j][0], sc[j][1]));
            rmax1 = fmaxf(rmax1, fmaxf(sc[j][2], sc[j][3]));
        }
        rmax0 = fmaxf(rmax0, __shfl_xor_sync(0xffffffffu, rmax0, 1));
        rmax0 = fmaxf(rmax0, __shfl_xor_sync(0xffffffffu, rmax0, 2));
        rmax1 = fmaxf(rmax1, __shfl_xor_sync(0xffffffffu, rmax1, 1));
        rmax1 = fmaxf(rmax1, __shfl_xor_sync(0xffffffffu, rmax1, 2));

        float mn0 = fmaxf(fmaxf(m0, rmax0), -1e28f);
        float mn1 = fmaxf(fmaxf(m1, rmax1), -1e28f);
        float esc0 = ex2f(m0 - mn0);
        float esc1 = ex2f(m1 - mn1);

        float rs0 = 0.0f, rs1 = 0.0f;
        #pragma unroll
        for (int j = 0; j < 8; ++j) {
            float p0 = ex2f(sc[j][0] - mn0);
            float p1 = ex2f(sc[j][1] - mn0);
            float p2 = ex2f(sc[j][2] - mn1);
            float p3 = ex2f(sc[j][3] - mn1);
            rs0 += p0 + p1;
            rs1 += p2 + p3;
            int row0 = w * 16 + g;
            unsigned i0 = (unsigned)(row0 * 64 + ((j ^ g) << 3) + 2 * t);
            *(__half2*)(Psh + i0)           = __floats2half2_rn(p0, p1);
            *(__half2*)(Psh + i0 + 8 * 64)  = __floats2half2_rn(p2, p3);
        }
        rs0 += __shfl_xor_sync(0xffffffffu, rs0, 1);
        rs0 += __shfl_xor_sync(0xffffffffu, rs0, 2);
        rs1 += __shfl_xor_sync(0xffffffffu, rs1, 1);
        rs1 += __shfl_xor_sync(0xffffffffu, rs1, 2);

        l0 = l0 * esc0 + rs0;
        l1 = l1 * esc1 + rs1;
        m0 = mn0;
        m1 = mn1;
        #pragma unroll
        for (int j = 0; j < 8; ++j) {
            oa[j][0] *= esc0; oa[j][1] *= esc0;
            oa[j][2] *= esc1; oa[j][3] *= esc1;
        }
        __syncwarp();                           // P rows are warp-private

        // O += P V : 16 x 64 per warp
        #pragma unroll
        for (int kg = 0; kg < 4; ++kg) {
            unsigned pa[4];
            const unsigned axc = (unsigned)(((2 * kg + ac) ^ r8) << 4);
            ldsm4(pa[0], pa[1], pa[2], pa[3],
                  sbase + SM_PB + pRow + axc);
            const unsigned bxc = (unsigned)(((2 * kg + bc) ^ r8) << 4);
            #pragma unroll
            for (int p = 0; p < 4; ++p) {
                unsigned b0[2], b1[2];
                ldsm4(b0[0], b0[1], b1[0], b1[1],
                      vT + kRow + (unsigned)(p * 2048) + bxc);
                mma_f16(oa[2 * p],     pa, b0);
                mma_f16(oa[2 * p + 1], pa, b1);
            }
        }
        buf ^= 1;
    }

    const int b = bh >> 4, h = bh & 15;
    const float inv0 = 1.0f / l0;
    const float inv1 = 1.0f / l1;
    __half* d0 = g_o + ((size_t)b * SEQ + r0) * DM + h * HD;
    __half* d1 = g_o + ((size_t)b * SEQ + r1) * DM + h * HD;
    #pragma unroll
    for (int j = 0; j < 8; ++j) {
        int col = j * 8 + (t << 1);
        *(__half2*)(d0 + col) = __floats2half2_rn(oa[j][0] * inv0, oa[j][1] * inv0);
        *(__half2*)(d1 + col) = __floats2half2_rn(oa[j][2] * inv1, oa[j][3] * inv1);
    }
    #undef ASTAGE
    #undef KBASE
}

// ---------------------------------------------------------------------------
extern "C" void kernel_launch(void* const* d_in, const int* in_sizes, int n_in,
                              void* d_out, int out_size)
{
    const float* x     = (const float*)d_in[0];
    const float* w_qkv = (const float*)d_in[1];
    const float* w_out = (const float*)d_in[2];
    float* out = (float*)d_out;

    cudaFuncSetAttribute(gemm_f16<true>,  cudaFuncAttributeMaxDynamicSharedMemorySize, GEMM_SMEM);
    cudaFuncSetAttribute(gemm_f16<false>, cudaFuncAttributeMaxDynamicSharedMemorySize, GEMM_SMEM);
    cudaFuncSetAttribute(attn_f16,        cudaFuncAttributeMaxDynamicSharedMemorySize, ATT_SMEM);

    // 0) fp16-convert all GEMM inputs once
    prep_f16<<<(unsigned)((NX + NW1 + NW2) / 4 / 256), 256>>>(x, w_qkv, w_out);
    // 1) QKV projection -> g_q/g_k/g_vt (v transposed), fp16
    gemm_f16<true><<<dim3(3072 / 128, 8192 / 128), 256, GEMM_SMEM>>>(nullptr);
    // 2) fp16 tensor-core flash attention (256q blocks) -> g_o
    attn_f16<<<dim3(SEQ / QB, BATCH * NH), 512, ATT_SMEM>>>();
    // 3) output projection -> d_out (f32)
    gemm_f16<false><<<dim3(1024 / 128, 8192 / 128), 256, GEMM_SMEM>>>(out);
}

// round 17
// speedup vs baseline: 1.1387x; 1.1387x over previous
#include <cuda_runtime.h>
#include <cuda_fp16.h>
#include <cstdint>

#define WINDOW   512
#define PREFIX   16
#define SEQ      4096
#define NH       16
#define BATCH    2
#define DM       1024
#define HD       64

#define NX  ((size_t)BATCH * SEQ * DM)
#define NW1 ((size_t)3 * DM * DM)
#define NW2 ((size_t)DM * DM)

// Scratch (device globals; allocation APIs are forbidden). All fp16.
__device__ __half g_q [(size_t)BATCH * NH * SEQ * HD];  // pre-scaled 0.125*log2e, [bh][s][d]
__device__ __half g_k [(size_t)BATCH * NH * SEQ * HD];  // [bh][s][d]
__device__ __half g_vt[(size_t)BATCH * NH * HD * SEQ];  // TRANSPOSED [bh][d][s]
__device__ __half g_o [(size_t)BATCH * SEQ * DM];       // [b][s][h*64+d]
__device__ __half g_x [NX];                             // fp16 copy of x
__device__ __half g_w1[NW1];                            // fp16 copy of w_qkv
__device__ __half g_w2[NW2];                            // fp16 copy of w_out

// ---------------------------------------------------------------------------
__device__ __forceinline__ void cp_async16(unsigned smem_dst, const void* gsrc) {
    asm volatile("cp.async.cg.shared.global [%0], [%1], 16;\n" :: "r"(smem_dst), "l"(gsrc));
}
__device__ __forceinline__ void cp_commit() { asm volatile("cp.async.commit_group;\n"); }
template<int N>
__device__ __forceinline__ void cp_wait() {
    asm volatile("cp.async.wait_group %0;\n" :: "n"(N));
}

__device__ __forceinline__ void mma_f16(float* c, const unsigned* a, const unsigned* b) {
    asm volatile(
        "mma.sync.aligned.m16n8k16.row.col.f32.f16.f16.f32 "
        "{%0,%1,%2,%3}, {%4,%5,%6,%7}, {%8,%9}, {%0,%1,%2,%3};\n"
        : "+f"(c[0]), "+f"(c[1]), "+f"(c[2]), "+f"(c[3])
        : "r"(a[0]), "r"(a[1]), "r"(a[2]), "r"(a[3]), "r"(b[0]), "r"(b[1]));
}

__device__ __forceinline__ void ldsm4(unsigned& r0, unsigned& r1, unsigned& r2, unsigned& r3,
                                      unsigned addr) {
    asm volatile("ldmatrix.sync.aligned.m8n8.x4.shared.b16 {%0,%1,%2,%3}, [%4];"
                 : "=r"(r0), "=r"(r1), "=r"(r2), "=r"(r3) : "r"(addr));
}

__device__ __forceinline__ float ex2f(float x) {
    float r;
    asm("ex2.approx.ftz.f32 %0, %1;" : "=f"(r) : "f"(x));
    return r;
}

__device__ __forceinline__ unsigned packh2(float a, float b) {
    __half2 h = __floats2half2_rn(a, b);
    return *(unsigned*)&h;
}

// ---------------------------------------------------------------------------
// Prep: fp16-convert x, w_qkv, w_out into scratch.
// ---------------------------------------------------------------------------
__global__ __launch_bounds__(256)
void prep_f16(const float* __restrict__ x,
              const float* __restrict__ wq,
              const float* __restrict__ wo)
{
    size_t i = (size_t)blockIdx.x * 256 + threadIdx.x;
    const size_t nx = NX / 4, nw1 = NW1 / 4;
    const float4* src;
    __half* dst;
    size_t j;
    if (i < nx)            { src = (const float4*)x;  dst = g_x;  j = i; }
    else if (i < nx + nw1) { src = (const float4*)wq; dst = g_w1; j = i - nx; }
    else                   { src = (const float4*)wo; dst = g_w2; j = i - nx - nw1; }
    float4 v = src[j];
    *(__half2*)(dst + 4 * j)     = __floats2half2_rn(v.x, v.y);
    *(__half2*)(dst + 4 * j + 2) = __floats2half2_rn(v.z, v.w);
}

// ---------------------------------------------------------------------------
// FP16 tensor-core GEMM (NT): round-11 shape (the best of six variants).
// 3-stage cp.async pipeline, XOR-swizzled smem, ldmatrix, m16n8k16.
// Block 128x128, 8 warps (2m x 4n), warp tile 64x32, KT=64.
// ---------------------------------------------------------------------------
#define KT     64
#define NTILE  (1024 / KT)                  // 16
#define NSTG   3
#define TILEB  (128 * 128)                  // 16384 bytes per matrix per stage
#define GEMM_SMEM (NSTG * 2 * TILEB)        // 98304 bytes

#define QSCALE 0.18033688f                  // 0.125 * log2(e)  (base-2 softmax)

template<bool QKV>
__global__ __launch_bounds__(256, 2)
void gemm_f16(float* __restrict__ Cout)
{
    extern __shared__ char smc[];

    const __half* A = QKV ? g_x  : g_o;
    const __half* B = QKV ? g_w1 : g_w2;

    const int tid  = threadIdx.x;
    const int lane = tid & 31;
    const int wid  = tid >> 5;
    const int wm   = wid >> 2;
    const int wn   = wid & 3;
    const int m0   = blockIdx.y << 7;
    const int n0   = blockIdx.x << 7;
    const int g    = lane >> 2;
    const int t    = lane & 3;
    const int r8   = lane & 7;
    const int sel  = lane >> 3;

    float acc[4][4][4];
    #pragma unroll
    for (int i = 0; i < 4; ++i)
        #pragma unroll
        for (int j = 0; j < 4; ++j)
            #pragma unroll
            for (int r = 0; r < 4; ++r) acc[i][j][r] = 0.0f;

    const unsigned sA = (unsigned)__cvta_generic_to_shared(smc);
    const unsigned sB = sA + NSTG * TILEB;

    const unsigned aRow = (unsigned)((wm * 64 + ((sel & 1) << 3) + r8) * 128);
    const unsigned bRow = (unsigned)((wn * 32 + ((sel >> 1) << 3) + r8) * 128);
    const int ac = sel >> 1;
    const int bc = sel & 1;

    #define GSTAGE(k0, s)                                                        \
        do {                                                                     \
            _Pragma("unroll")                                                    \
            for (int it2 = 0; it2 < 4; ++it2) {                                  \
                int idx = tid + (it2 << 8);                                      \
                int row = idx >> 3;                                              \
                int c   = idx & 7;                                               \
                unsigned off = (unsigned)(row * 128 + ((c ^ (row & 7)) << 4))    \
                             + (unsigned)(s) * TILEB;                            \
                cp_async16(sA + off, A + (size_t)(m0 + row) * 1024 + (k0) + c * 8); \
                cp_async16(sB + off, B + (size_t)(n0 + row) * 1024 + (k0) + c * 8); \
            }                                                                    \
            cp_commit();                                                         \
        } while (0)

    GSTAGE(0 * KT, 0);
    GSTAGE(1 * KT, 1);

    for (int kt = 0; kt < NTILE; ++kt) {
        if (kt < NTILE - 1) cp_wait<1>();
        else                cp_wait<0>();
        __syncthreads();
        if (kt + 2 < NTILE) GSTAGE((kt + 2) * KT, (kt + 2) % NSTG);

        const unsigned aT = sA + (unsigned)(kt % NSTG) * TILEB;
        const unsigned bT = sB + (unsigned)(kt % NSTG) * TILEB;

        #pragma unroll
        for (int kg = 0; kg < 4; ++kg) {
            const unsigned axc = (unsigned)(((2 * kg + ac) ^ r8) << 4);
            const unsigned bxc = (unsigned)(((2 * kg + bc) ^ r8) << 4);
            unsigned af[4][4];
            #pragma unroll
            for (int im = 0; im < 4; ++im)
                ldsm4(af[im][0], af[im][1], af[im][2], af[im][3],
                      aT + aRow + (unsigned)(im * 2048) + axc);
            #pragma unroll
            for (int p = 0; p < 2; ++p) {
                unsigned b0[2], b1[2];
                ldsm4(b0[0], b0[1], b1[0], b1[1],
                      bT + bRow + (unsigned)(p * 2048) + bxc);
                #pragma unroll
                for (int im = 0; im < 4; ++im) {
                    mma_f16(acc[im][2 * p],     af[im], b0);
                    mma_f16(acc[im][2 * p + 1], af[im], b1);
                }
            }
        }
    }

    #pragma unroll
    for (int im = 0; im < 4; ++im) {
        #pragma unroll
        for (int jn = 0; jn < 4; ++jn) {
            int row = m0 + wm * 64 + im * 16 + g;
            int col = n0 + wn * 32 + jn * 8 + (t << 1);
            if (QKV) {
                int part = col >> 10;            // 0:q 1:k 2:v
                float sc = (part == 0) ? QSCALE : 1.0f;
                __half2 h0 = __floats2half2_rn(acc[im][jn][0] * sc, acc[im][jn][1] * sc);
                __half2 h1 = __floats2half2_rn(acc[im][jn][2] * sc, acc[im][jn][3] * sc);
                int nn = col & 1023;
                int h  = nn >> 6;
                int d  = nn & 63;
                int bb = row >> 12, s = row & 4095;
                if (part == 2) {
                    __half* dst = g_vt + ((size_t)(bb * NH + h) * HD + d) * SEQ + s;
                    dst[0]       = __low2half(h0);
                    dst[SEQ]     = __high2half(h0);
                    dst[8]       = __low2half(h1);
                    dst[SEQ + 8] = __high2half(h1);
                } else {
                    __half* dst = (part == 0) ? g_q : g_k;
                    size_t base = (((size_t)(bb * NH + h)) * SEQ) * HD + d;
                    *(__half2*)(dst + base + (size_t)s * HD)       = h0;
                    *(__half2*)(dst + base + (size_t)(s + 8) * HD) = h1;
                }
            } else {
                *(float2*)(Cout + (size_t)row * DM + col) =
                    make_float2(acc[im][jn][0], acc[im][jn][1]);
                *(float2*)(Cout + (size_t)(row + 8) * DM + col) =
                    make_float2(acc[im][jn][2], acc[im][jn][3]);
            }
        }
    }
    #undef GSTAGE
}

// ---------------------------------------------------------------------------
// FP16 tensor-core flash attention: 128 queries/block, REGISTER-RESIDENT P.
// Lane (g,t)'s scores sc[j][0..3] = rows (g,g+8) x cols (j*8+2t, +1) are
// exactly the m16n8k16 A-fragment for PV k16-group kg = j/2:
//   pa[kg][0,1] = pack(sc[2kg][0..1]), pack(sc[2kg][2..3])
//   pa[kg][2,3] = pack(sc[2kg+1][0..1]), pack(sc[2kg+1][2..3])
// -> no P smem round-trip. Q in registers, double-buffered K/V^T, base-2 softmax.
// Smem: K[2][64][128B] | Vt[2][64][128B] = 32 KB.
// ---------------------------------------------------------------------------
#define KVB   8192
#define ATT_SMEM (4 * KVB)                 // 32768 bytes

__global__ __launch_bounds__(256, 2)
void attn_f16()
{
    extern __shared__ char smc[];

    const int tid  = threadIdx.x;
    const int lane = tid & 31;
    const int w    = tid >> 5;
    const int g    = lane >> 2;
    const int t    = lane & 3;
    const int r8   = lane & 7;
    const int sel  = lane >> 3;
    const int bh   = blockIdx.y;
    const int t0   = blockIdx.x << 7;

    const __half* Kg  = g_k  + (size_t)bh * SEQ * HD;
    const __half* Vtg = g_vt + (size_t)bh * HD * SEQ;

    const unsigned sbase = (unsigned)__cvta_generic_to_shared(smc);

    const unsigned kRow = (unsigned)((((sel >> 1) << 3) + r8) * 128);
    const int bc = sel & 1;

    const int rmin = t0 + w * 16;
    const int r0 = rmin + g;
    const int r1 = r0 + 8;

    unsigned qa[4][4];
    {
        const __half* q0 = g_q + (size_t)bh * SEQ * HD + (size_t)r0 * HD;
        #pragma unroll
        for (int kg = 0; kg < 4; ++kg) {
            qa[kg][0] = *(const unsigned*)(q0 + kg * 16 + 2 * t);
            qa[kg][1] = *(const unsigned*)(q0 + 512 + kg * 16 + 2 * t);
            qa[kg][2] = *(const unsigned*)(q0 + kg * 16 + 2 * t + 8);
            qa[kg][3] = *(const unsigned*)(q0 + 512 + kg * 16 + 2 * t + 8);
        }
    }

    #define ASTAGE(kbase, s)                                                     \
        do {                                                                     \
            _Pragma("unroll")                                                    \
            for (int it2 = 0; it2 < 2; ++it2) {                                  \
                int idx = tid + (it2 << 8);                                      \
                int row = idx >> 3;                                              \
                int c   = idx & 7;                                               \
                unsigned off = (unsigned)(row * 128 + ((c ^ (row & 7)) << 4))    \
                             + (unsigned)(s) * KVB;                              \
                cp_async16(sbase + off,            Kg  + (size_t)((kbase) + row) * 64 + c * 8); \
                cp_async16(sbase + off + 2 * KVB,  Vtg + (size_t)row * SEQ + (kbase) + c * 8);  \
            }                                                                    \
            cp_commit();                                                         \
        } while (0)

    float oa[8][4];
    #pragma unroll
    for (int j = 0; j < 8; ++j)
        #pragma unroll
        for (int r = 0; r < 4; ++r) oa[j][r] = 0.0f;
    float m0 = -1e30f, m1 = -1e30f, l0 = 0.0f, l1 = 0.0f;

    int lo = t0 - (WINDOW - 1); if (lo < 0) lo = 0;
    const int lo_tile = lo >> 6;
    const int hi_tile = (t0 + 127) >> 6;
    const int extra   = (lo_tile > 0) ? 1 : 0;
    const int ntiles  = hi_tile - lo_tile + 1 + extra;

    #define KBASE(i) ((extra ? (((i) == 0) ? 0 : (lo_tile + (i) - 1)) : (lo_tile + (i))) << 6)

    ASTAGE(KBASE(0), 0);

    int buf = 0;
    for (int it = 0; it < ntiles; ++it) {
        const int kbase = KBASE(it);
        cp_wait<0>();
        __syncthreads();
        if (it + 1 < ntiles) ASTAGE(KBASE(it + 1), buf ^ 1);

        const unsigned kT = sbase + (unsigned)buf * KVB;
        const unsigned vT = kT + 2 * KVB;

        float sc[8][4];
        #pragma unroll
        for (int j = 0; j < 8; ++j)
            #pragma unroll
            for (int r = 0; r < 4; ++r) sc[j][r] = 0.0f;

        #pragma unroll
        for (int kg = 0; kg < 4; ++kg) {
            const unsigned bxc = (unsigned)(((2 * kg + bc) ^ r8) << 4);
            #pragma unroll
            for (int p = 0; p < 4; ++p) {
                unsigned b0[2], b1[2];
                ldsm4(b0[0], b0[1], b1[0], b1[1],
                      kT + kRow + (unsigned)(p * 2048) + bxc);
                mma_f16(sc[2 * p],     qa[kg], b0);
                mma_f16(sc[2 * p + 1], qa[kg], b1);
            }
        }

        const bool full = (kbase + 63 <= rmin) && ((rmin + 15 - kbase) < WINDOW);
        if (!full) {
            #pragma unroll
            for (int j = 0; j < 8; ++j) {
                int kc0 = kbase + j * 8 + (t << 1);
                int kc1 = kc0 + 1;
                bool a00 = (kc0 <= r0) && ((kc0 < PREFIX) || ((r0 - kc0) < WINDOW));
                bool a01 = (kc1 <= r0) && ((kc1 < PREFIX) || ((r0 - kc1) < WINDOW));
                bool a10 = (kc0 <= r1) && ((kc0 < PREFIX) || ((r1 - kc0) < WINDOW));
                bool a11 = (kc1 <= r1) && ((kc1 < PREFIX) || ((r1 - kc1) < WINDOW));
                if (!a00) sc[j][0] = -1e30f;
                if (!a01) sc[j][1] = -1e30f;
                if (!a10) sc[j][2] = -1e30f;
                if (!a11) sc[j][3] = -1e30f;
            }
        }
        float rmax0 = -1e30f, rmax1 = -1e30f;
        #pragma unroll
        for (int j = 0; j < 8; ++j) {
            rmax0 = fmaxf(rmax0, fmaxf(sc[j][0], sc[j][1]));
            rmax1 = fmaxf(rmax1, fmaxf(sc[j][2], sc[j][3]));
        }
        rmax0 = fmaxf(rmax0, __shfl_xor_sync(0xffffffffu, rmax0, 1));
        rmax0 = fmaxf(rmax0, __shfl_xor_sync(0xffffffffu, rmax0, 2));
        rmax1 = fmaxf(rmax1, __shfl_xor_sync(0xffffffffu, rmax1, 1));
        rmax1 = fmaxf(rmax1, __shfl_xor_sync(0xffffffffu, rmax1, 2));

        float mn0 = fmaxf(fmaxf(m0, rmax0), -1e28f);
        float mn1 = fmaxf(fmaxf(m1, rmax1), -1e28f);
        float esc0 = ex2f(m0 - mn0);
        float esc1 = ex2f(m1 - mn1);

        unsigned pa[4][4];
        float rs0 = 0.0f, rs1 = 0.0f;
        #pragma unroll
        for (int j = 0; j < 8; ++j) {
            float p0 = ex2f(sc[j][0] - mn0);
            float p1 = ex2f(sc[j][1] - mn0);
            float p2 = ex2f(sc[j][2] - mn1);
            float p3 = ex2f(sc[j][3] - mn1);
            rs0 += p0 + p1;
            rs1 += p2 + p3;
            const int kg = j >> 1;
            const int hf = (j & 1) << 1;
            pa[kg][hf]     = packh2(p0, p1);   // rows g   : cols j*8+2t, +1
            pa[kg][hf + 1] = packh2(p2, p3);   // rows g+8 : cols j*8+2t, +1
        }
        rs0 += __shfl_xor_sync(0xffffffffu, rs0, 1);
        rs0 += __shfl_xor_sync(0xffffffffu, rs0, 2);
        rs1 += __shfl_xor_sync(0xffffffffu, rs1, 1);
        rs1 += __shfl_xor_sync(0xffffffffu, rs1, 2);

        l0 = l0 * esc0 + rs0;
        l1 = l1 * esc1 + rs1;
        m0 = mn0;
        m1 = mn1;
        #pragma unroll
        for (int j = 0; j < 8; ++j) {
            oa[j][0] *= esc0; oa[j][1] *= esc0;
            oa[j][2] *= esc1; oa[j][3] *= esc1;
        }

        // NOTE: pa order must be {a0=rowg half0, a1=rowg+8 half0, a2=rowg half1, a3=rowg+8 half1}
        // pa[kg] = {pack(sc[2kg][0,1]), pack(sc[2kg][2,3]), pack(sc[2kg+1][0,1]), pack(sc[2kg+1][2,3])}
        // which is exactly what the loop above built (hf=0 -> regs 0,1 ; hf=2 -> regs 2,3).

        #pragma unroll
        for (int kg = 0; kg < 4; ++kg) {
            const unsigned bxc = (unsigned)(((2 * kg + bc) ^ r8) << 4);
            #pragma unroll
            for (int p = 0; p < 4; ++p) {
                unsigned b0[2], b1[2];
                ldsm4(b0[0], b0[1], b1[0], b1[1],
                      vT + kRow + (unsigned)(p * 2048) + bxc);
                mma_f16(oa[2 * p],     pa[kg], b0);
                mma_f16(oa[2 * p + 1], pa[kg], b1);
            }
        }
        buf ^= 1;
    }

    const int b = bh >> 4, h = bh & 15;
    const float inv0 = 1.0f / l0;
    const float inv1 = 1.0f / l1;
    __half* d0 = g_o + ((size_t)b * SEQ + r0) * DM + h * HD;
    __half* d1 = g_o + ((size_t)b * SEQ + r1) * DM + h * HD;
    #pragma unroll
    for (int j = 0; j < 8; ++j) {
        int col = j * 8 + (t << 1);
        *(__half2*)(d0 + col) = __floats2half2_rn(oa[j][0] * inv0, oa[j][1] * inv0);
        *(__half2*)(d1 + col) = __floats2half2_rn(oa[j][2] * inv1, oa[j][3] * inv1);
    }
    #undef ASTAGE
    #undef KBASE
}

// ---------------------------------------------------------------------------
extern "C" void kernel_launch(void* const* d_in, const int* in_sizes, int n_in,
                              void* d_out, int out_size)
{
    const float* x     = (const float*)d_in[0];
    const float* w_qkv = (const float*)d_in[1];
    const float* w_out = (const float*)d_in[2];
    float* out = (float*)d_out;

    cudaFuncSetAttribute(gemm_f16<true>,  cudaFuncAttributeMaxDynamicSharedMemorySize, GEMM_SMEM);
    cudaFuncSetAttribute(gemm_f16<false>, cudaFuncAttributeMaxDynamicSharedMemorySize, GEMM_SMEM);
    cudaFuncSetAttribute(attn_f16,        cudaFuncAttributeMaxDynamicSharedMemorySize, ATT_SMEM);

    // 0) fp16-convert all GEMM inputs once
    prep_f16<<<(unsigned)((NX + NW1 + NW2) / 4 / 256), 256>>>(x, w_qkv, w_out);
    // 1) QKV projection -> g_q/g_k/g_vt (v transposed), fp16
    gemm_f16<true><<<dim3(3072 / 128, 8192 / 128), 256, GEMM_SMEM>>>(nullptr);
    // 2) fp16 tensor-core flash attention (register-resident P) -> g_o
    attn_f16<<<dim3(SEQ / 128, BATCH * NH), 256, ATT_SMEM>>>();
    // 3) output projection -> d_out (f32)
    gemm_f16<false><<<dim3(1024 / 128, 8192 / 128), 256, GEMM_SMEM>>>(out);
}